// round 6
// baseline (speedup 1.0000x reference)
#include <cuda_runtime.h>
#include <math.h>

#define NMAX 50000
#define FDIM 96
#define FD4  24          // float4s per feature row
#define EMAX 800000
#define DEPTH 3
#define OUTC 384         // (DEPTH+1)*FDIM
#define LEAKY 0.2f

// ---------------- device scratch ----------------
__device__ float4 g_fa[NMAX * FD4];
__device__ float4 g_fb[NMAX * FD4];
__device__ float4 g_eterm[NMAX];          // es0, es1, en0, en1
__device__ float2 g_sc[EMAX];             // fallback scratch (deg > 64 rows)
__device__ int    g_deg[NMAX];
__device__ int    g_rowstart[NMAX];
__device__ int    g_cursor[NMAX];
__device__ int    g_csrcol[EMAX];
__device__ int    g_total;
__device__ int    g_is64;

__device__ __forceinline__ float leaky(float x) {
    return x > 0.0f ? x : LEAKY * x;
}

// ---------------- dtype detection (parallel) ----------------
__global__ void k_detect(const int* __restrict__ adj_words, int nwords) {
    __shared__ int sh[1024];
    int t = threadIdx.x;
    int acc = 0;
    int lim = min(nwords, 65536);
    for (int i = 1 + 2 * t; i < lim; i += 2048) acc |= adj_words[i];
    sh[t] = acc;
    __syncthreads();
    for (int off = 512; off > 0; off >>= 1) {
        if (t < off) sh[t] |= sh[t + off];
        __syncthreads();
    }
    if (t == 0) g_is64 = (sh[0] == 0) ? 1 : 0;
}

__global__ void k_zerodeg(int n) {
    int gid = blockIdx.x * blockDim.x + threadIdx.x;
    for (int i = gid; i < n; i += gridDim.x * blockDim.x)
        g_deg[i] = 0;
    if (gid == 0) g_total = 0;
}

// ---------------- CSR build (atomic slice assignment, no scan) ------------
__global__ void k_hist(const void* __restrict__ adj, int e, int n) {
    int is64 = g_is64;
    for (int i = blockIdx.x * blockDim.x + threadIdx.x; i < e;
         i += gridDim.x * blockDim.x) {
        int r;
        if (is64) r = (int)((const longlong2*)adj)[i].x;
        else      r = ((const int*)adj)[2 * i];
        if ((unsigned)r < (unsigned)n) atomicAdd(&g_deg[r], 1);
    }
}

__global__ void k_assign(int n) {
    for (int i = blockIdx.x * blockDim.x + threadIdx.x; i < n;
         i += gridDim.x * blockDim.x) {
        int d = g_deg[i];
        int base = atomicAdd(&g_total, d);
        g_rowstart[i] = base;
        g_cursor[i]   = base;
    }
}

__global__ void k_scatter(const void* __restrict__ adj, int e, int n) {
    int is64 = g_is64;
    for (int i = blockIdx.x * blockDim.x + threadIdx.x; i < e;
         i += gridDim.x * blockDim.x) {
        int r, c;
        if (is64) {
            longlong2 rc = ((const longlong2*)adj)[i];
            r = (int)rc.x; c = (int)rc.y;
        } else {
            int2 rc = ((const int2*)adj)[i];
            r = rc.x; c = rc.y;
        }
        if ((unsigned)r >= (unsigned)n) continue;
        if ((unsigned)c >= (unsigned)n) c = 0;
        int pos = atomicAdd(&g_cursor[r], 1);
        if (pos < EMAX) g_csrcol[pos] = c;
    }
}

// ---------------- initial features (diag rows unique -> direct store) -----
__global__ void k_init(const float* __restrict__ node_f,
                       const void* __restrict__ sidx,
                       const float* __restrict__ sval,
                       float* __restrict__ out, int n) {
    int gw = (blockIdx.x * blockDim.x + threadIdx.x) >> 5;
    int lane = threadIdx.x & 31;
    if (gw >= n) return;
    int is64 = g_is64;
    int r, c;
    if (is64) {
        longlong2 rc = ((const longlong2*)sidx)[gw];
        r = (int)rc.x; c = (int)rc.y;
    } else {
        int2 rc = ((const int2*)sidx)[gw];
        r = rc.x; c = rc.y;
    }
    if ((unsigned)r >= (unsigned)n || (unsigned)c >= (unsigned)n) return;
    if (lane >= FD4) return;
    float v = sval[gw];
    float4 s = ((const float4*)node_f)[(long)c * FD4 + lane];
    float4 x;
    x.x = fmaxf(v * s.x, 0.0f);
    x.y = fmaxf(v * s.y, 0.0f);
    x.z = fmaxf(v * s.z, 0.0f);
    x.w = fmaxf(v * s.w, 0.0f);
    g_fa[(long)r * FD4 + lane] = x;
    ((float4*)(out + (long)r * OUTC))[lane] = x;
}

// ---------------- per-node attention logits ----------------
__global__ void k_eterm(int src, const float* __restrict__ as,
                        const float* __restrict__ an, int n) {
    int gw = (blockIdx.x * blockDim.x + threadIdx.x) >> 5;
    int lane = threadIdx.x & 31;
    if (gw >= n) return;
    const float4* feat = src ? g_fb : g_fa;
    const float4* as4 = (const float4*)as;
    const float4* an4 = (const float4*)an;

    float s0 = 0.f, s1 = 0.f, n0 = 0.f, n1 = 0.f;
    if (lane < FD4) {
        float4 f = feat[(long)gw * FD4 + lane];
        float4 a;
        a = as4[lane];        s0 = f.x*a.x + f.y*a.y + f.z*a.z + f.w*a.w;
        a = as4[FD4 + lane];  s1 = f.x*a.x + f.y*a.y + f.z*a.z + f.w*a.w;
        a = an4[lane];        n0 = f.x*a.x + f.y*a.y + f.z*a.z + f.w*a.w;
        a = an4[FD4 + lane];  n1 = f.x*a.x + f.y*a.y + f.z*a.z + f.w*a.w;
    }
#pragma unroll
    for (int off = 16; off > 0; off >>= 1) {
        s0 += __shfl_xor_sync(0xffffffffu, s0, off);
        s1 += __shfl_xor_sync(0xffffffffu, s1, off);
        n0 += __shfl_xor_sync(0xffffffffu, n0, off);
        n1 += __shfl_xor_sync(0xffffffffu, n1, off);
    }
    if (lane == 0) g_eterm[gw] = make_float4(s0, s1, n0, n1);
}

// ---------------- layer: softmax + aggregate (2 heads fused) --------------
__global__ void __launch_bounds__(256) k_layer(int src, float* __restrict__ out,
                                               int layer, int n) {
    int gw = (blockIdx.x * blockDim.x + threadIdx.x) >> 5;
    int lane = threadIdx.x & 31;
    if (gw >= n) return;
    const float4* feat = src ? g_fb : g_fa;
    float4* feat_out   = src ? g_fa : g_fb;

    int start = g_rowstart[gw];
    int deg   = g_deg[gw];
    int end   = start + deg;

    float4 er = g_eterm[gw];
    float es0 = er.x, es1 = er.y;

    bool small = (deg <= 64);
    float x0a = -INFINITY, x1a = -INFINITY;   // per-lane score regs
    float x0b = -INFINITY, x1b = -INFINITY;

    float m0 = -INFINITY, m1 = -INFINITY;
    if (small) {
        int j0 = start + lane;
        if (j0 < end) {
            int c = g_csrcol[j0];
            float4 ec = g_eterm[c];
            x0a = leaky(es0 + ec.z);
            x1a = leaky(es1 + ec.w);
            m0 = x0a; m1 = x1a;
        }
        int j1 = j0 + 32;
        if (j1 < end) {
            int c = g_csrcol[j1];
            float4 ec = g_eterm[c];
            x0b = leaky(es0 + ec.z);
            x1b = leaky(es1 + ec.w);
            m0 = fmaxf(m0, x0b); m1 = fmaxf(m1, x1b);
        }
    } else {
        for (int j = start + lane; j < end; j += 32) {
            int c = g_csrcol[j];
            float4 ec = g_eterm[c];
            float x0 = leaky(es0 + ec.z);
            float x1 = leaky(es1 + ec.w);
            g_sc[j] = make_float2(x0, x1);
            m0 = fmaxf(m0, x0);
            m1 = fmaxf(m1, x1);
        }
    }
#pragma unroll
    for (int off = 16; off > 0; off >>= 1) {
        m0 = fmaxf(m0, __shfl_xor_sync(0xffffffffu, m0, off));
        m1 = fmaxf(m1, __shfl_xor_sync(0xffffffffu, m1, off));
    }

    float sum0 = 0.0f, sum1 = 0.0f;
    if (small) {
        x0a = __expf(x0a - m0);  x1a = __expf(x1a - m1);   // exp(-inf)=0 pads
        x0b = __expf(x0b - m0);  x1b = __expf(x1b - m1);
        sum0 = x0a + x0b;
        sum1 = x1a + x1b;
    } else {
        for (int j = start + lane; j < end; j += 32) {
            float2 s = g_sc[j];
            float e0 = __expf(s.x - m0);
            float e1 = __expf(s.y - m1);
            sum0 += e0; sum1 += e1;
            g_sc[j] = make_float2(e0, e1);
        }
    }
#pragma unroll
    for (int off = 16; off > 0; off >>= 1) {
        sum0 += __shfl_xor_sync(0xffffffffu, sum0, off);
        sum1 += __shfl_xor_sync(0xffffffffu, sum1, off);
    }
    float inv0 = sum0 > 0.0f ? 1.0f / sum0 : 0.0f;
    float inv1 = sum1 > 0.0f ? 1.0f / sum1 : 0.0f;

    // pass 3: weighted aggregation, 4 edges in flight
    float4 A0 = make_float4(0.f, 0.f, 0.f, 0.f);
    float4 A1 = make_float4(0.f, 0.f, 0.f, 0.f);
    bool act = (lane < FD4);

    int i = 0;
    for (; i + 4 <= deg; i += 4) {
        int c0 = g_csrcol[start + i];
        int c1 = g_csrcol[start + i + 1];
        int c2 = g_csrcol[start + i + 2];
        int c3 = g_csrcol[start + i + 3];
        float w00, w01, w02, w03, w10, w11, w12, w13;
        if (small) {
            // weight for edge idx lives in lane idx&31, reg idx>>5
            float s0r = ((i >> 5) == 0) ? x0a : x0b;   // i..i+3 same reg iff i%32<=28; i multiple of 4 so yes
            float s1r = ((i >> 5) == 0) ? x1a : x1b;
            w00 = __shfl_sync(0xffffffffu, s0r, (i    ) & 31);
            w01 = __shfl_sync(0xffffffffu, s0r, (i + 1) & 31);
            w02 = __shfl_sync(0xffffffffu, s0r, (i + 2) & 31);
            w03 = __shfl_sync(0xffffffffu, s0r, (i + 3) & 31);
            w10 = __shfl_sync(0xffffffffu, s1r, (i    ) & 31);
            w11 = __shfl_sync(0xffffffffu, s1r, (i + 1) & 31);
            w12 = __shfl_sync(0xffffffffu, s1r, (i + 2) & 31);
            w13 = __shfl_sync(0xffffffffu, s1r, (i + 3) & 31);
        } else {
            float2 a = g_sc[start + i];
            float2 b = g_sc[start + i + 1];
            float2 c = g_sc[start + i + 2];
            float2 d = g_sc[start + i + 3];
            w00 = a.x; w10 = a.y; w01 = b.x; w11 = b.y;
            w02 = c.x; w12 = c.y; w03 = d.x; w13 = d.y;
        }
        float4 f0 = make_float4(0.f,0.f,0.f,0.f), f1 = f0, f2 = f0, f3 = f0;
        if (act) {
            f0 = feat[(long)c0 * FD4 + lane];
            f1 = feat[(long)c1 * FD4 + lane];
            f2 = feat[(long)c2 * FD4 + lane];
            f3 = feat[(long)c3 * FD4 + lane];
        }
        A0.x += w00*f0.x + w01*f1.x + w02*f2.x + w03*f3.x;
        A0.y += w00*f0.y + w01*f1.y + w02*f2.y + w03*f3.y;
        A0.z += w00*f0.z + w01*f1.z + w02*f2.z + w03*f3.z;
        A0.w += w00*f0.w + w01*f1.w + w02*f2.w + w03*f3.w;
        A1.x += w10*f0.x + w11*f1.x + w12*f2.x + w13*f3.x;
        A1.y += w10*f0.y + w11*f1.y + w12*f2.y + w13*f3.y;
        A1.z += w10*f0.z + w11*f1.z + w12*f2.z + w13*f3.z;
        A1.w += w10*f0.w + w11*f1.w + w12*f2.w + w13*f3.w;
    }
    for (; i < deg; i++) {
        int c0 = g_csrcol[start + i];
        float w0, w1;
        if (small) {
            float s0r = ((i >> 5) == 0) ? x0a : x0b;
            float s1r = ((i >> 5) == 0) ? x1a : x1b;
            w0 = __shfl_sync(0xffffffffu, s0r, i & 31);
            w1 = __shfl_sync(0xffffffffu, s1r, i & 31);
        } else {
            float2 a = g_sc[start + i];
            w0 = a.x; w1 = a.y;
        }
        float4 f0 = make_float4(0.f,0.f,0.f,0.f);
        if (act) f0 = feat[(long)c0 * FD4 + lane];
        A0.x += w0*f0.x; A0.y += w0*f0.y; A0.z += w0*f0.z; A0.w += w0*f0.w;
        A1.x += w1*f0.x; A1.y += w1*f0.y; A1.z += w1*f0.z; A1.w += w1*f0.w;
    }

    if (act) {
        float4 v;
        v.x = fmaxf(0.5f * (A0.x * inv0 + A1.x * inv1), 0.0f);
        v.y = fmaxf(0.5f * (A0.y * inv0 + A1.y * inv1), 0.0f);
        v.z = fmaxf(0.5f * (A0.z * inv0 + A1.z * inv1), 0.0f);
        v.w = fmaxf(0.5f * (A0.w * inv0 + A1.w * inv1), 0.0f);
        feat_out[(long)gw * FD4 + lane] = v;
        ((float4*)(out + (long)gw * OUTC + (layer + 1) * FDIM))[lane] = v;
    }
}

// ---------------- launch ----------------
extern "C" void kernel_launch(void* const* d_in, const int* in_sizes, int n_in,
                              void* d_out, int out_size) {
    const float* node_f = (const float*)d_in[0];
    const void*  adj    = d_in[1];
    const void*  sidx   = d_in[2];
    const float* sval   = (const float*)d_in[3];
    const float* as_k   = (const float*)d_in[4];
    const float* an_k   = (const float*)d_in[5];
    float*       out    = (float*)d_out;

    int n = in_sizes[0] / FDIM;
    int e = in_sizes[1] / 2;
    if (n > NMAX) n = NMAX;
    if (e > EMAX) e = EMAX;

    const int T = 256;
    int gridN = (n + T - 1) / T;
    int gridE = (e + T - 1) / T;
    int gridW = (n + (T / 32) - 1) / (T / 32);

    k_detect<<<1, 1024>>>((const int*)adj, in_sizes[1]);
    k_zerodeg<<<gridN, T>>>(n);
    k_hist<<<gridE, T>>>(adj, e, n);
    k_assign<<<gridN, T>>>(n);
    k_scatter<<<gridE, T>>>(adj, e, n);
    k_init<<<gridW, T>>>(node_f, sidx, sval, out, n);

    int src = 0;
    for (int d = 0; d < DEPTH; d++) {
        k_eterm<<<gridW, T>>>(src, as_k, an_k, n);
        k_layer<<<gridW, T>>>(src, out, d, n);
        src ^= 1;
    }
}

// round 8
// speedup vs baseline: 1.2792x; 1.2792x over previous
#include <cuda_runtime.h>
#include <math.h>

#define NMAX 50000
#define FDIM 96
#define FD4  24          // float4s per feature row
#define EMAX 800000
#define DEPTH 3
#define OUTC 384         // (DEPTH+1)*FDIM
#define LEAKY 0.2f

// ---------------- device scratch ----------------
__device__ float4 g_fa[NMAX * FD4];
__device__ float4 g_fb[NMAX * FD4];
__device__ float4 g_et_a[NMAX];           // eterm ping
__device__ float4 g_et_b[NMAX];           // eterm pong
__device__ float2 g_sc[EMAX];             // per-edge scores / exp weights
__device__ int    g_deg[NMAX];
__device__ int    g_rowstart[NMAX];
__device__ int    g_cursor[NMAX];
__device__ int    g_csrcol[EMAX];
__device__ int    g_total;
__device__ int    g_is64;

__device__ __forceinline__ float leaky(float x) {
    return x > 0.0f ? x : LEAKY * x;
}

// compute 4 attention dots from a register-resident feature float4 (lane<FD4)
// and store to et[row]; all 32 lanes must participate in shuffles.
__device__ __forceinline__ void eterm_from_regs(
    float4* __restrict__ et, int row, float4 f, bool act, int lane,
    const float4* __restrict__ as4, const float4* __restrict__ an4) {
    float s0 = 0.f, s1 = 0.f, n0 = 0.f, n1 = 0.f;
    if (act) {
        float4 a;
        a = as4[lane];        s0 = f.x*a.x + f.y*a.y + f.z*a.z + f.w*a.w;
        a = as4[FD4 + lane];  s1 = f.x*a.x + f.y*a.y + f.z*a.z + f.w*a.w;
        a = an4[lane];        n0 = f.x*a.x + f.y*a.y + f.z*a.z + f.w*a.w;
        a = an4[FD4 + lane];  n1 = f.x*a.x + f.y*a.y + f.z*a.z + f.w*a.w;
    }
#pragma unroll
    for (int off = 16; off > 0; off >>= 1) {
        s0 += __shfl_xor_sync(0xffffffffu, s0, off);
        s1 += __shfl_xor_sync(0xffffffffu, s1, off);
        n0 += __shfl_xor_sync(0xffffffffu, n0, off);
        n1 += __shfl_xor_sync(0xffffffffu, n1, off);
    }
    if (lane == 0) et[row] = make_float4(s0, s1, n0, n1);
}

// ---------------- dtype detection + zero deg ----------------
__global__ void k_detect(const int* __restrict__ adj_words, int nwords, int n) {
    __shared__ int sh[256];
    int t = threadIdx.x;
    int gid = blockIdx.x * blockDim.x + t;
    for (int i = gid; i < n; i += gridDim.x * blockDim.x)
        g_deg[i] = 0;
    if (gid == 0) g_total = 0;
    if (blockIdx.x == 0) {
        int acc = 0;
        int lim = min(nwords, 16384);
        for (int i = 1 + 2 * t; i < lim; i += 512) acc |= adj_words[i];
        sh[t] = acc;
        __syncthreads();
        for (int off = 128; off > 0; off >>= 1) {
            if (t < off) sh[t] |= sh[t + off];
            __syncthreads();
        }
        if (t == 0) g_is64 = (sh[0] == 0) ? 1 : 0;
    }
}

// ---------------- CSR build (atomic slice assignment, no scan) ------------
__global__ void k_hist(const void* __restrict__ adj, int e, int n) {
    int is64 = g_is64;
    for (int i = blockIdx.x * blockDim.x + threadIdx.x; i < e;
         i += gridDim.x * blockDim.x) {
        int r;
        if (is64) r = (int)((const longlong2*)adj)[i].x;
        else      r = ((const int*)adj)[2 * i];
        if ((unsigned)r < (unsigned)n) atomicAdd(&g_deg[r], 1);
    }
}

__global__ void k_assign(int n) {
    for (int i = blockIdx.x * blockDim.x + threadIdx.x; i < n;
         i += gridDim.x * blockDim.x) {
        int d = g_deg[i];
        int base = atomicAdd(&g_total, d);
        g_rowstart[i] = base;
        g_cursor[i]   = base;
    }
}

__global__ void k_scatter(const void* __restrict__ adj, int e, int n) {
    int is64 = g_is64;
    for (int i = blockIdx.x * blockDim.x + threadIdx.x; i < e;
         i += gridDim.x * blockDim.x) {
        int r, c;
        if (is64) {
            longlong2 rc = ((const longlong2*)adj)[i];
            r = (int)rc.x; c = (int)rc.y;
        } else {
            int2 rc = ((const int2*)adj)[i];
            r = rc.x; c = rc.y;
        }
        if ((unsigned)r >= (unsigned)n) continue;
        if ((unsigned)c >= (unsigned)n) c = 0;
        int pos = atomicAdd(&g_cursor[r], 1);
        if (pos < EMAX) g_csrcol[pos] = c;
    }
}

// ---------------- initial features + fused eterm (writes et_a) ------------
__global__ void k_init(const float* __restrict__ node_f,
                       const void* __restrict__ sidx,
                       const float* __restrict__ sval,
                       const float* __restrict__ as, const float* __restrict__ an,
                       float* __restrict__ out, int n) {
    int gw = (blockIdx.x * blockDim.x + threadIdx.x) >> 5;
    int lane = threadIdx.x & 31;
    if (gw >= n) return;
    int is64 = g_is64;
    int r, c;
    if (is64) {
        longlong2 rc = ((const longlong2*)sidx)[gw];
        r = (int)rc.x; c = (int)rc.y;
    } else {
        int2 rc = ((const int2*)sidx)[gw];
        r = rc.x; c = rc.y;
    }
    if ((unsigned)r >= (unsigned)n || (unsigned)c >= (unsigned)n) return;
    bool act = (lane < FD4);
    float v = sval[gw];
    float4 x = make_float4(0.f, 0.f, 0.f, 0.f);
    if (act) {
        float4 s = ((const float4*)node_f)[(long)c * FD4 + lane];
        x.x = fmaxf(v * s.x, 0.0f);
        x.y = fmaxf(v * s.y, 0.0f);
        x.z = fmaxf(v * s.z, 0.0f);
        x.w = fmaxf(v * s.w, 0.0f);
        g_fa[(long)r * FD4 + lane] = x;
        ((float4*)(out + (long)r * OUTC))[lane] = x;
    }
    eterm_from_regs(g_et_a, r, x, act, lane, (const float4*)as, (const float4*)an);
}

// ---------------- layer: softmax + aggregate + fused next-layer eterm -----
__global__ void __launch_bounds__(256) k_layer(int src, float* __restrict__ out,
                                               const float* __restrict__ as,
                                               const float* __restrict__ an,
                                               int layer, int n) {
    int gw = (blockIdx.x * blockDim.x + threadIdx.x) >> 5;
    int lane = threadIdx.x & 31;
    if (gw >= n) return;
    const float4* feat  = src ? g_fb : g_fa;
    float4* feat_out    = src ? g_fa : g_fb;
    const float4* et_in = src ? g_et_b : g_et_a;
    float4* et_out      = src ? g_et_a : g_et_b;

    int start = g_rowstart[gw];
    int deg   = g_deg[gw];
    int end   = start + deg;

    float4 er = et_in[gw];
    float es0 = er.x, es1 = er.y;

    // pass 1: gather eterm once, compute leaky scores -> scratch; track max
    float m0 = -INFINITY, m1 = -INFINITY;
    for (int j = start + lane; j < end; j += 32) {
        int c = g_csrcol[j];
        float4 ec = et_in[c];
        float x0 = leaky(es0 + ec.z);
        float x1 = leaky(es1 + ec.w);
        g_sc[j] = make_float2(x0, x1);
        m0 = fmaxf(m0, x0);
        m1 = fmaxf(m1, x1);
    }
#pragma unroll
    for (int off = 16; off > 0; off >>= 1) {
        m0 = fmaxf(m0, __shfl_xor_sync(0xffffffffu, m0, off));
        m1 = fmaxf(m1, __shfl_xor_sync(0xffffffffu, m1, off));
    }

    // pass 2: sequential read, exp, write back unnormalized weights
    float sum0 = 0.0f, sum1 = 0.0f;
    for (int j = start + lane; j < end; j += 32) {
        float2 s = g_sc[j];
        float e0 = __expf(s.x - m0);
        float e1 = __expf(s.y - m1);
        sum0 += e0;
        sum1 += e1;
        g_sc[j] = make_float2(e0, e1);
    }
#pragma unroll
    for (int off = 16; off > 0; off >>= 1) {
        sum0 += __shfl_xor_sync(0xffffffffu, sum0, off);
        sum1 += __shfl_xor_sync(0xffffffffu, sum1, off);
    }
    float inv0 = sum0 > 0.0f ? 1.0f / sum0 : 0.0f;
    float inv1 = sum1 > 0.0f ? 1.0f / sum1 : 0.0f;

    // pass 3: weighted aggregation, 4 edges in flight
    float4 A0 = make_float4(0.f, 0.f, 0.f, 0.f);
    float4 A1 = make_float4(0.f, 0.f, 0.f, 0.f);
    bool act = (lane < FD4);

    int j = start;
    for (; j + 4 <= end; j += 4) {
        int c0 = g_csrcol[j];
        int c1 = g_csrcol[j + 1];
        int c2 = g_csrcol[j + 2];
        int c3 = g_csrcol[j + 3];
        float2 w0 = g_sc[j];
        float2 w1 = g_sc[j + 1];
        float2 w2 = g_sc[j + 2];
        float2 w3 = g_sc[j + 3];
        float4 f0 = make_float4(0.f,0.f,0.f,0.f), f1 = f0, f2 = f0, f3 = f0;
        if (act) {
            f0 = feat[(long)c0 * FD4 + lane];
            f1 = feat[(long)c1 * FD4 + lane];
            f2 = feat[(long)c2 * FD4 + lane];
            f3 = feat[(long)c3 * FD4 + lane];
        }
        A0.x += w0.x*f0.x + w1.x*f1.x + w2.x*f2.x + w3.x*f3.x;
        A0.y += w0.x*f0.y + w1.x*f1.y + w2.x*f2.y + w3.x*f3.y;
        A0.z += w0.x*f0.z + w1.x*f1.z + w2.x*f2.z + w3.x*f3.z;
        A0.w += w0.x*f0.w + w1.x*f1.w + w2.x*f2.w + w3.x*f3.w;
        A1.x += w0.y*f0.x + w1.y*f1.x + w2.y*f2.x + w3.y*f3.x;
        A1.y += w0.y*f0.y + w1.y*f1.y + w2.y*f2.y + w3.y*f3.y;
        A1.z += w0.y*f0.z + w1.y*f1.z + w2.y*f2.z + w3.y*f3.z;
        A1.w += w0.y*f0.w + w1.y*f1.w + w2.y*f2.w + w3.y*f3.w;
    }
    for (; j < end; j++) {
        int c0 = g_csrcol[j];
        float2 w0 = g_sc[j];
        float4 f0 = make_float4(0.f,0.f,0.f,0.f);
        if (act) f0 = feat[(long)c0 * FD4 + lane];
        A0.x += w0.x*f0.x; A0.y += w0.x*f0.y; A0.z += w0.x*f0.z; A0.w += w0.x*f0.w;
        A1.x += w0.y*f0.x; A1.y += w0.y*f0.y; A1.z += w0.y*f0.z; A1.w += w0.y*f0.w;
    }

    float4 v = make_float4(0.f, 0.f, 0.f, 0.f);
    if (act) {
        v.x = fmaxf(0.5f * (A0.x * inv0 + A1.x * inv1), 0.0f);
        v.y = fmaxf(0.5f * (A0.y * inv0 + A1.y * inv1), 0.0f);
        v.z = fmaxf(0.5f * (A0.z * inv0 + A1.z * inv1), 0.0f);
        v.w = fmaxf(0.5f * (A0.w * inv0 + A1.w * inv1), 0.0f);
        feat_out[(long)gw * FD4 + lane] = v;
        ((float4*)(out + (long)gw * OUTC + (layer + 1) * FDIM))[lane] = v;
    }
    // fused eterm for the next layer, into the OTHER buffer (no race)
    if (layer + 1 < DEPTH)
        eterm_from_regs(et_out, gw, v, act, lane,
                        (const float4*)as, (const float4*)an);
}

// ---------------- launch ----------------
extern "C" void kernel_launch(void* const* d_in, const int* in_sizes, int n_in,
                              void* d_out, int out_size) {
    const float* node_f = (const float*)d_in[0];
    const void*  adj    = d_in[1];
    const void*  sidx   = d_in[2];
    const float* sval   = (const float*)d_in[3];
    const float* as_k   = (const float*)d_in[4];
    const float* an_k   = (const float*)d_in[5];
    float*       out    = (float*)d_out;

    int n = in_sizes[0] / FDIM;
    int e = in_sizes[1] / 2;
    if (n > NMAX) n = NMAX;
    if (e > EMAX) e = EMAX;

    const int T = 256;
    int gridN = (n + T - 1) / T;
    int gridE = (e + T - 1) / T;
    int gridW = (n + (T / 32) - 1) / (T / 32);

    k_detect<<<gridN, T>>>((const int*)adj, in_sizes[1], n);
    k_hist<<<gridE, T>>>(adj, e, n);
    k_assign<<<gridN, T>>>(n);
    k_scatter<<<gridE, T>>>(adj, e, n);
    k_init<<<gridW, T>>>(node_f, sidx, sval, as_k, an_k, out, n);

    int src = 0;
    for (int d = 0; d < DEPTH; d++) {
        k_layer<<<gridW, T>>>(src, out, as_k, an_k, d, n);
        src ^= 1;
    }
}

// round 9
// speedup vs baseline: 1.3122x; 1.0258x over previous
#include <cuda_runtime.h>
#include <math.h>

#define NMAX 50000
#define FDIM 96
#define FD4  24          // float4s per feature row
#define EMAX 800000
#define DEPTH 3
#define OUTC 384         // (DEPTH+1)*FDIM
#define LEAKY 0.2f

// ---------------- device scratch ----------------
__device__ float4 g_fa[NMAX * FD4];
__device__ float4 g_fb[NMAX * FD4];
__device__ float4 g_et_a[NMAX];           // eterm ping
__device__ float4 g_et_b[NMAX];           // eterm pong
__device__ float2 g_sc[EMAX];             // per-edge exp weights
__device__ int    g_deg[NMAX];
__device__ int    g_rowstart[NMAX];
__device__ int    g_cursor[NMAX];
__device__ int    g_csrcol[EMAX];
__device__ int    g_total;

__device__ __forceinline__ float leaky(float x) {
    return x > 0.0f ? x : LEAKY * x;
}

// Per-block int64-vs-int32 detection: odd 32-bit words of an int64 index
// array (values < 2^31) are all zero; for int32 data they are random/arange
// column indices -> never all zero. Must be called by all threads (has sync).
__device__ __forceinline__ int block_is64(const int* __restrict__ words,
                                          int nwords) {
    __shared__ int s_flag;
    if (threadIdx.x == 0) {
        int acc = 0;
        int lim = min(nwords, 128);
        for (int i = 1; i < lim; i += 2) acc |= words[i];
        s_flag = (acc == 0) ? 1 : 0;
    }
    __syncthreads();
    return s_flag;
}

// compute 4 attention dots from a register-resident feature float4 (lane<FD4)
__device__ __forceinline__ void eterm_from_regs(
    float4* __restrict__ et, int row, float4 f, bool act, int lane,
    const float4* __restrict__ as4, const float4* __restrict__ an4) {
    float s0 = 0.f, s1 = 0.f, n0 = 0.f, n1 = 0.f;
    if (act) {
        float4 a;
        a = as4[lane];        s0 = f.x*a.x + f.y*a.y + f.z*a.z + f.w*a.w;
        a = as4[FD4 + lane];  s1 = f.x*a.x + f.y*a.y + f.z*a.z + f.w*a.w;
        a = an4[lane];        n0 = f.x*a.x + f.y*a.y + f.z*a.z + f.w*a.w;
        a = an4[FD4 + lane];  n1 = f.x*a.x + f.y*a.y + f.z*a.z + f.w*a.w;
    }
#pragma unroll
    for (int off = 16; off > 0; off >>= 1) {
        s0 += __shfl_xor_sync(0xffffffffu, s0, off);
        s1 += __shfl_xor_sync(0xffffffffu, s1, off);
        n0 += __shfl_xor_sync(0xffffffffu, n0, off);
        n1 += __shfl_xor_sync(0xffffffffu, n1, off);
    }
    if (lane == 0) et[row] = make_float4(s0, s1, n0, n1);
}

// ---------------- zero deg + counter ----------------
__global__ void k_zero(int n) {
    int gid = blockIdx.x * blockDim.x + threadIdx.x;
    for (int i = gid; i < n; i += gridDim.x * blockDim.x)
        g_deg[i] = 0;
    if (gid == 0) g_total = 0;
}

// ---------------- CSR build (atomic slice assignment, no scan) ------------
__global__ void k_hist(const void* __restrict__ adj, int e, int n) {
    int is64 = block_is64((const int*)adj, 2 * e * 2);
    for (int i = blockIdx.x * blockDim.x + threadIdx.x; i < e;
         i += gridDim.x * blockDim.x) {
        int r;
        if (is64) r = (int)((const longlong2*)adj)[i].x;
        else      r = ((const int*)adj)[2 * i];
        if ((unsigned)r < (unsigned)n) atomicAdd(&g_deg[r], 1);
    }
}

__global__ void k_assign(int n) {
    for (int i = blockIdx.x * blockDim.x + threadIdx.x; i < n;
         i += gridDim.x * blockDim.x) {
        int d = g_deg[i];
        int base = atomicAdd(&g_total, d);
        g_rowstart[i] = base;
        g_cursor[i]   = base;
    }
}

__global__ void k_scatter(const void* __restrict__ adj, int e, int n) {
    int is64 = block_is64((const int*)adj, 2 * e * 2);
    for (int i = blockIdx.x * blockDim.x + threadIdx.x; i < e;
         i += gridDim.x * blockDim.x) {
        int r, c;
        if (is64) {
            longlong2 rc = ((const longlong2*)adj)[i];
            r = (int)rc.x; c = (int)rc.y;
        } else {
            int2 rc = ((const int2*)adj)[i];
            r = rc.x; c = rc.y;
        }
        if ((unsigned)r >= (unsigned)n) continue;
        if ((unsigned)c >= (unsigned)n) c = 0;
        int pos = atomicAdd(&g_cursor[r], 1);
        if (pos < EMAX) g_csrcol[pos] = c;
    }
}

// ---------------- initial features + fused eterm (writes et_a) ------------
__global__ void k_init(const float* __restrict__ node_f,
                       const void* __restrict__ sidx,
                       const float* __restrict__ sval,
                       const float* __restrict__ as, const float* __restrict__ an,
                       float* __restrict__ out, int n) {
    int is64 = block_is64((const int*)sidx, 2 * n * 2);
    int gw = (blockIdx.x * blockDim.x + threadIdx.x) >> 5;
    int lane = threadIdx.x & 31;
    if (gw >= n) return;
    int r, c;
    if (is64) {
        longlong2 rc = ((const longlong2*)sidx)[gw];
        r = (int)rc.x; c = (int)rc.y;
    } else {
        int2 rc = ((const int2*)sidx)[gw];
        r = rc.x; c = rc.y;
    }
    if ((unsigned)r >= (unsigned)n || (unsigned)c >= (unsigned)n) return;
    bool act = (lane < FD4);
    float v = sval[gw];
    float4 x = make_float4(0.f, 0.f, 0.f, 0.f);
    if (act) {
        float4 s = ((const float4*)node_f)[(long)c * FD4 + lane];
        x.x = fmaxf(v * s.x, 0.0f);
        x.y = fmaxf(v * s.y, 0.0f);
        x.z = fmaxf(v * s.z, 0.0f);
        x.w = fmaxf(v * s.w, 0.0f);
        g_fa[(long)r * FD4 + lane] = x;
        ((float4*)(out + (long)r * OUTC))[lane] = x;
    }
    eterm_from_regs(g_et_a, r, x, act, lane, (const float4*)as, (const float4*)an);
}

// ---------------- layer: direct-exp softmax + aggregate + fused eterm -----
__global__ void __launch_bounds__(256) k_layer(int src, float* __restrict__ out,
                                               const float* __restrict__ as,
                                               const float* __restrict__ an,
                                               int layer, int n) {
    int gw = (blockIdx.x * blockDim.x + threadIdx.x) >> 5;
    int lane = threadIdx.x & 31;
    if (gw >= n) return;
    const float4* feat  = src ? g_fb : g_fa;
    float4* feat_out    = src ? g_fa : g_fb;
    const float4* et_in = src ? g_et_b : g_et_a;
    float4* et_out      = src ? g_et_a : g_et_b;

    int start = g_rowstart[gw];
    int deg   = g_deg[gw];
    int end   = start + deg;

    float4 er = et_in[gw];
    float es0 = er.x, es1 = er.y;

    // pass 1: gather eterm once, compute exp(leaky(score)) -> scratch + sums
    // (scores are bounded |x| ~ O(10): raw exp is fp32-safe; identical after
    //  normalization to the max-subtracted reference)
    float sum0 = 0.0f, sum1 = 0.0f;
    for (int j = start + lane; j < end; j += 32) {
        int c = g_csrcol[j];
        float4 ec = et_in[c];
        float w0 = __expf(leaky(es0 + ec.z));
        float w1 = __expf(leaky(es1 + ec.w));
        g_sc[j] = make_float2(w0, w1);
        sum0 += w0;
        sum1 += w1;
    }
#pragma unroll
    for (int off = 16; off > 0; off >>= 1) {
        sum0 += __shfl_xor_sync(0xffffffffu, sum0, off);
        sum1 += __shfl_xor_sync(0xffffffffu, sum1, off);
    }
    float inv0 = sum0 > 0.0f ? 1.0f / sum0 : 0.0f;
    float inv1 = sum1 > 0.0f ? 1.0f / sum1 : 0.0f;

    // pass 2: weighted aggregation, 4 edges in flight
    float4 A0 = make_float4(0.f, 0.f, 0.f, 0.f);
    float4 A1 = make_float4(0.f, 0.f, 0.f, 0.f);
    bool act = (lane < FD4);

    int j = start;
    for (; j + 4 <= end; j += 4) {
        int c0 = g_csrcol[j];
        int c1 = g_csrcol[j + 1];
        int c2 = g_csrcol[j + 2];
        int c3 = g_csrcol[j + 3];
        float2 w0 = g_sc[j];
        float2 w1 = g_sc[j + 1];
        float2 w2 = g_sc[j + 2];
        float2 w3 = g_sc[j + 3];
        float4 f0 = make_float4(0.f,0.f,0.f,0.f), f1 = f0, f2 = f0, f3 = f0;
        if (act) {
            f0 = feat[(long)c0 * FD4 + lane];
            f1 = feat[(long)c1 * FD4 + lane];
            f2 = feat[(long)c2 * FD4 + lane];
            f3 = feat[(long)c3 * FD4 + lane];
        }
        A0.x += w0.x*f0.x + w1.x*f1.x + w2.x*f2.x + w3.x*f3.x;
        A0.y += w0.x*f0.y + w1.x*f1.y + w2.x*f2.y + w3.x*f3.y;
        A0.z += w0.x*f0.z + w1.x*f1.z + w2.x*f2.z + w3.x*f3.z;
        A0.w += w0.x*f0.w + w1.x*f1.w + w2.x*f2.w + w3.x*f3.w;
        A1.x += w0.y*f0.x + w1.y*f1.x + w2.y*f2.x + w3.y*f3.x;
        A1.y += w0.y*f0.y + w1.y*f1.y + w2.y*f2.y + w3.y*f3.y;
        A1.z += w0.y*f0.z + w1.y*f1.z + w2.y*f2.z + w3.y*f3.z;
        A1.w += w0.y*f0.w + w1.y*f1.w + w2.y*f2.w + w3.y*f3.w;
    }
    for (; j < end; j++) {
        int c0 = g_csrcol[j];
        float2 w0 = g_sc[j];
        float4 f0 = make_float4(0.f,0.f,0.f,0.f);
        if (act) f0 = feat[(long)c0 * FD4 + lane];
        A0.x += w0.x*f0.x; A0.y += w0.x*f0.y; A0.z += w0.x*f0.z; A0.w += w0.x*f0.w;
        A1.x += w0.y*f0.x; A1.y += w0.y*f0.y; A1.z += w0.y*f0.z; A1.w += w0.y*f0.w;
    }

    float4 v = make_float4(0.f, 0.f, 0.f, 0.f);
    if (act) {
        v.x = fmaxf(0.5f * (A0.x * inv0 + A1.x * inv1), 0.0f);
        v.y = fmaxf(0.5f * (A0.y * inv0 + A1.y * inv1), 0.0f);
        v.z = fmaxf(0.5f * (A0.z * inv0 + A1.z * inv1), 0.0f);
        v.w = fmaxf(0.5f * (A0.w * inv0 + A1.w * inv1), 0.0f);
        feat_out[(long)gw * FD4 + lane] = v;
        ((float4*)(out + (long)gw * OUTC + (layer + 1) * FDIM))[lane] = v;
    }
    // fused eterm for the next layer, into the OTHER buffer (no race)
    if (layer + 1 < DEPTH)
        eterm_from_regs(et_out, gw, v, act, lane,
                        (const float4*)as, (const float4*)an);
}

// ---------------- launch ----------------
extern "C" void kernel_launch(void* const* d_in, const int* in_sizes, int n_in,
                              void* d_out, int out_size) {
    const float* node_f = (const float*)d_in[0];
    const void*  adj    = d_in[1];
    const void*  sidx   = d_in[2];
    const float* sval   = (const float*)d_in[3];
    const float* as_k   = (const float*)d_in[4];
    const float* an_k   = (const float*)d_in[5];
    float*       out    = (float*)d_out;

    int n = in_sizes[0] / FDIM;
    int e = in_sizes[1] / 2;
    if (n > NMAX) n = NMAX;
    if (e > EMAX) e = EMAX;

    const int T = 256;
    int gridN = (n + T - 1) / T;
    int gridE = (e + T - 1) / T;
    int gridW = (n + (T / 32) - 1) / (T / 32);

    k_zero<<<gridN, T>>>(n);
    k_hist<<<gridE, T>>>(adj, e, n);
    k_assign<<<gridN, T>>>(n);
    k_scatter<<<gridE, T>>>(adj, e, n);
    k_init<<<gridW, T>>>(node_f, sidx, sval, as_k, an_k, out, n);

    int src = 0;
    for (int d = 0; d < DEPTH; d++) {
        k_layer<<<gridW, T>>>(src, out, as_k, an_k, d, n);
        src ^= 1;
    }
}

// round 10
// speedup vs baseline: 1.3317x; 1.0149x over previous
#include <cuda_runtime.h>
#include <math.h>

#define NMAX 50000
#define FDIM 96
#define FD4  24          // float4s per feature row
#define EMAX 800000
#define DEPTH 3
#define OUTC 384         // (DEPTH+1)*FDIM
#define LEAKY 0.2f
#define SMW  64          // smem weight slots per warp (deg <= SMW fast path)

// ---------------- device scratch ----------------
__device__ float4 g_fa[NMAX * FD4];
__device__ float4 g_fb[NMAX * FD4];
__device__ float4 g_et_a[NMAX];           // eterm ping
__device__ float4 g_et_b[NMAX];           // eterm pong
__device__ float2 g_sc[EMAX];             // fallback weights (deg > SMW)
__device__ int2   g_edge[EMAX];           // compacted (r,c) int32 edges
__device__ int    g_deg[NMAX];
__device__ int    g_rowstart[NMAX];
__device__ int    g_cursor[NMAX];
__device__ int    g_csrcol[EMAX];
__device__ int    g_total;

__device__ __forceinline__ float leaky(float x) {
    return x > 0.0f ? x : LEAKY * x;
}

// Per-block int64-vs-int32 detection (odd words of int64 < 2^31 are all 0).
__device__ __forceinline__ int block_is64(const int* __restrict__ words,
                                          int nwords) {
    __shared__ int s_flag;
    if (threadIdx.x == 0) {
        int acc = 0;
        int lim = min(nwords, 128);
        for (int i = 1; i < lim; i += 2) acc |= words[i];
        s_flag = (acc == 0) ? 1 : 0;
    }
    __syncthreads();
    return s_flag;
}

// compute 4 attention dots from a register-resident feature float4 (lane<FD4)
__device__ __forceinline__ void eterm_from_regs(
    float4* __restrict__ et, int row, float4 f, bool act, int lane,
    const float4* __restrict__ as4, const float4* __restrict__ an4) {
    float s0 = 0.f, s1 = 0.f, n0 = 0.f, n1 = 0.f;
    if (act) {
        float4 a;
        a = as4[lane];        s0 = f.x*a.x + f.y*a.y + f.z*a.z + f.w*a.w;
        a = as4[FD4 + lane];  s1 = f.x*a.x + f.y*a.y + f.z*a.z + f.w*a.w;
        a = an4[lane];        n0 = f.x*a.x + f.y*a.y + f.z*a.z + f.w*a.w;
        a = an4[FD4 + lane];  n1 = f.x*a.x + f.y*a.y + f.z*a.z + f.w*a.w;
    }
#pragma unroll
    for (int off = 16; off > 0; off >>= 1) {
        s0 += __shfl_xor_sync(0xffffffffu, s0, off);
        s1 += __shfl_xor_sync(0xffffffffu, s1, off);
        n0 += __shfl_xor_sync(0xffffffffu, n0, off);
        n1 += __shfl_xor_sync(0xffffffffu, n1, off);
    }
    if (lane == 0) et[row] = make_float4(s0, s1, n0, n1);
}

// ---------------- zero deg + counter ----------------
__global__ void k_zero(int n) {
    int gid = blockIdx.x * blockDim.x + threadIdx.x;
    for (int i = gid; i < n; i += gridDim.x * blockDim.x)
        g_deg[i] = 0;
    if (gid == 0) g_total = 0;
}

// ---------------- CSR build: hist + edge compaction ----------------
__global__ void k_hist(const void* __restrict__ adj, int e, int n) {
    int is64 = block_is64((const int*)adj, 2 * e * 2);
    for (int i = blockIdx.x * blockDim.x + threadIdx.x; i < e;
         i += gridDim.x * blockDim.x) {
        int r, c;
        if (is64) {
            longlong2 rc = ((const longlong2*)adj)[i];
            r = (int)rc.x; c = (int)rc.y;
        } else {
            int2 rc = ((const int2*)adj)[i];
            r = rc.x; c = rc.y;
        }
        if ((unsigned)r >= (unsigned)n) { r = -1; }
        if ((unsigned)c >= (unsigned)n) { c = 0; }
        g_edge[i] = make_int2(r, c);
        if (r >= 0) atomicAdd(&g_deg[r], 1);
    }
}

__global__ void k_assign(int n) {
    for (int i = blockIdx.x * blockDim.x + threadIdx.x; i < n;
         i += gridDim.x * blockDim.x) {
        int d = g_deg[i];
        int base = atomicAdd(&g_total, d);
        g_rowstart[i] = base;
        g_cursor[i]   = base;
    }
}

__global__ void k_scatter(int e) {
    for (int i = blockIdx.x * blockDim.x + threadIdx.x; i < e;
         i += gridDim.x * blockDim.x) {
        int2 rc = g_edge[i];
        if (rc.x < 0) continue;
        int pos = atomicAdd(&g_cursor[rc.x], 1);
        if (pos < EMAX) g_csrcol[pos] = rc.y;
    }
}

// ---------------- initial features + fused eterm (writes et_a) ------------
__global__ void k_init(const float* __restrict__ node_f,
                       const void* __restrict__ sidx,
                       const float* __restrict__ sval,
                       const float* __restrict__ as, const float* __restrict__ an,
                       float* __restrict__ out, int n) {
    int is64 = block_is64((const int*)sidx, 2 * n * 2);
    int gw = (blockIdx.x * blockDim.x + threadIdx.x) >> 5;
    int lane = threadIdx.x & 31;
    if (gw >= n) return;
    int r, c;
    if (is64) {
        longlong2 rc = ((const longlong2*)sidx)[gw];
        r = (int)rc.x; c = (int)rc.y;
    } else {
        int2 rc = ((const int2*)sidx)[gw];
        r = rc.x; c = rc.y;
    }
    if ((unsigned)r >= (unsigned)n || (unsigned)c >= (unsigned)n) return;
    bool act = (lane < FD4);
    float v = sval[gw];
    float4 x = make_float4(0.f, 0.f, 0.f, 0.f);
    if (act) {
        float4 s = ((const float4*)node_f)[(long)c * FD4 + lane];
        x.x = fmaxf(v * s.x, 0.0f);
        x.y = fmaxf(v * s.y, 0.0f);
        x.z = fmaxf(v * s.z, 0.0f);
        x.w = fmaxf(v * s.w, 0.0f);
        g_fa[(long)r * FD4 + lane] = x;
        ((float4*)(out + (long)r * OUTC))[lane] = x;
    }
    eterm_from_regs(g_et_a, r, x, act, lane, (const float4*)as, (const float4*)an);
}

// ---------------- layer: direct-exp softmax + aggregate + fused eterm -----
__global__ void __launch_bounds__(256) k_layer(int src, float* __restrict__ out,
                                               const float* __restrict__ as,
                                               const float* __restrict__ an,
                                               int layer, int n) {
    __shared__ float2 s_w[8][SMW];        // 8 warps x 64 slots = 4KB
    int wslot = (threadIdx.x >> 5);
    int gw = (blockIdx.x * blockDim.x + threadIdx.x) >> 5;
    int lane = threadIdx.x & 31;
    if (gw >= n) return;
    const float4* feat  = src ? g_fb : g_fa;
    float4* feat_out    = src ? g_fa : g_fb;
    const float4* et_in = src ? g_et_b : g_et_a;
    float4* et_out      = src ? g_et_a : g_et_b;

    int start = g_rowstart[gw];
    int deg   = g_deg[gw];
    int end   = start + deg;
    bool small = (deg <= SMW);

    float4 er = et_in[gw];
    float es0 = er.x, es1 = er.y;

    // pass 1: gather eterm, exp(leaky(score)) -> smem (or g_sc) + sums
    float sum0 = 0.0f, sum1 = 0.0f;
    for (int j = start + lane; j < end; j += 32) {
        int c = g_csrcol[j];
        float4 ec = et_in[c];
        float w0 = __expf(leaky(es0 + ec.z));
        float w1 = __expf(leaky(es1 + ec.w));
        if (small) s_w[wslot][j - start] = make_float2(w0, w1);
        else       g_sc[j] = make_float2(w0, w1);
        sum0 += w0;
        sum1 += w1;
    }
#pragma unroll
    for (int off = 16; off > 0; off >>= 1) {
        sum0 += __shfl_xor_sync(0xffffffffu, sum0, off);
        sum1 += __shfl_xor_sync(0xffffffffu, sum1, off);
    }
    float inv0 = sum0 > 0.0f ? 1.0f / sum0 : 0.0f;
    float inv1 = sum1 > 0.0f ? 1.0f / sum1 : 0.0f;
    __syncwarp();

    // pass 2: weighted aggregation, 4 edges in flight
    float4 A0 = make_float4(0.f, 0.f, 0.f, 0.f);
    float4 A1 = make_float4(0.f, 0.f, 0.f, 0.f);
    bool act = (lane < FD4);

    int j = start;
    for (; j + 4 <= end; j += 4) {
        int i0 = j - start;
        int c0 = g_csrcol[j];
        int c1 = g_csrcol[j + 1];
        int c2 = g_csrcol[j + 2];
        int c3 = g_csrcol[j + 3];
        float2 w0, w1, w2, w3;
        if (small) {
            w0 = s_w[wslot][i0];
            w1 = s_w[wslot][i0 + 1];
            w2 = s_w[wslot][i0 + 2];
            w3 = s_w[wslot][i0 + 3];
        } else {
            w0 = g_sc[j]; w1 = g_sc[j + 1]; w2 = g_sc[j + 2]; w3 = g_sc[j + 3];
        }
        float4 f0 = make_float4(0.f,0.f,0.f,0.f), f1 = f0, f2 = f0, f3 = f0;
        if (act) {
            f0 = feat[(long)c0 * FD4 + lane];
            f1 = feat[(long)c1 * FD4 + lane];
            f2 = feat[(long)c2 * FD4 + lane];
            f3 = feat[(long)c3 * FD4 + lane];
        }
        A0.x += w0.x*f0.x + w1.x*f1.x + w2.x*f2.x + w3.x*f3.x;
        A0.y += w0.x*f0.y + w1.x*f1.y + w2.x*f2.y + w3.x*f3.y;
        A0.z += w0.x*f0.z + w1.x*f1.z + w2.x*f2.z + w3.x*f3.z;
        A0.w += w0.x*f0.w + w1.x*f1.w + w2.x*f2.w + w3.x*f3.w;
        A1.x += w0.y*f0.x + w1.y*f1.x + w2.y*f2.x + w3.y*f3.x;
        A1.y += w0.y*f0.y + w1.y*f1.y + w2.y*f2.y + w3.y*f3.y;
        A1.z += w0.y*f0.z + w1.y*f1.z + w2.y*f2.z + w3.y*f3.z;
        A1.w += w0.y*f0.w + w1.y*f1.w + w2.y*f2.w + w3.y*f3.w;
    }
    for (; j < end; j++) {
        int c0 = g_csrcol[j];
        float2 w0 = small ? s_w[wslot][j - start] : g_sc[j];
        float4 f0 = make_float4(0.f,0.f,0.f,0.f);
        if (act) f0 = feat[(long)c0 * FD4 + lane];
        A0.x += w0.x*f0.x; A0.y += w0.x*f0.y; A0.z += w0.x*f0.z; A0.w += w0.x*f0.w;
        A1.x += w0.y*f0.x; A1.y += w0.y*f0.y; A1.z += w0.y*f0.z; A1.w += w0.y*f0.w;
    }

    float4 v = make_float4(0.f, 0.f, 0.f, 0.f);
    if (act) {
        v.x = fmaxf(0.5f * (A0.x * inv0 + A1.x * inv1), 0.0f);
        v.y = fmaxf(0.5f * (A0.y * inv0 + A1.y * inv1), 0.0f);
        v.z = fmaxf(0.5f * (A0.z * inv0 + A1.z * inv1), 0.0f);
        v.w = fmaxf(0.5f * (A0.w * inv0 + A1.w * inv1), 0.0f);
        feat_out[(long)gw * FD4 + lane] = v;
        ((float4*)(out + (long)gw * OUTC + (layer + 1) * FDIM))[lane] = v;
    }
    if (layer + 1 < DEPTH)
        eterm_from_regs(et_out, gw, v, act, lane,
                        (const float4*)as, (const float4*)an);
}

// ---------------- launch ----------------
extern "C" void kernel_launch(void* const* d_in, const int* in_sizes, int n_in,
                              void* d_out, int out_size) {
    const float* node_f = (const float*)d_in[0];
    const void*  adj    = d_in[1];
    const void*  sidx   = d_in[2];
    const float* sval   = (const float*)d_in[3];
    const float* as_k   = (const float*)d_in[4];
    const float* an_k   = (const float*)d_in[5];
    float*       out    = (float*)d_out;

    int n = in_sizes[0] / FDIM;
    int e = in_sizes[1] / 2;
    if (n > NMAX) n = NMAX;
    if (e > EMAX) e = EMAX;

    const int T = 256;
    int gridN = (n + T - 1) / T;
    int gridE = (e + T - 1) / T;
    int gridW = (n + (T / 32) - 1) / (T / 32);

    k_zero<<<gridN, T>>>(n);
    k_hist<<<gridE, T>>>(adj, e, n);
    k_assign<<<gridN, T>>>(n);
    k_scatter<<<gridE, T>>>(e);
    k_init<<<gridW, T>>>(node_f, sidx, sval, as_k, an_k, out, n);

    int src = 0;
    for (int d = 0; d < DEPTH; d++) {
        k_layer<<<gridW, T>>>(src, out, as_k, an_k, d, n);
        src ^= 1;
    }
}